// round 11
// baseline (speedup 1.0000x reference)
#include <cuda_runtime.h>
#include <cuda_bf16.h>
#include <math.h>
#include <stdint.h>

#define B_ 4
#define T_ 4096
#define D_ 2048
#define H_ 128
#define M_TOT (B_*T_)
#define NSPLIT 4

// ---------------- device scratch (no allocations allowed) -------------------
__device__ __nv_bfloat16 g_xh[(size_t)M_TOT * D_];
__device__ __nv_bfloat16 g_xl[(size_t)M_TOT * D_];
__device__ __nv_bfloat16 g_wh[3 * H_ * D_];
__device__ __nv_bfloat16 g_wl[3 * H_ * D_];
__device__ __nv_bfloat16 g_qh[M_TOT * H_];
__device__ __nv_bfloat16 g_ql[M_TOT * H_];
__device__ __nv_bfloat16 g_kh[M_TOT * H_];
__device__ __nv_bfloat16 g_kl[M_TOT * H_];
__device__ __nv_bfloat16 g_vh[M_TOT * H_];
__device__ __nv_bfloat16 g_vl[M_TOT * H_];
__device__ float g_po[NSPLIT * (size_t)M_TOT * H_];
__device__ float g_pm[NSPLIT * M_TOT];
__device__ float g_pl[NSPLIT * M_TOT];

// ---------------- helpers ---------------------------------------------------
__device__ __forceinline__ uint32_t smem_u32(const void* p) {
    uint32_t a;
    asm("{ .reg .u64 t; cvta.to.shared.u64 t, %1; cvt.u32.u64 %0, t; }" : "=r"(a) : "l"(p));
    return a;
}

#define LDSM_X4(r0, r1, r2, r3, addr) \
    asm volatile("ldmatrix.sync.aligned.m8n8.x4.shared.b16 {%0,%1,%2,%3}, [%4];" \
                 : "=r"(r0), "=r"(r1), "=r"(r2), "=r"(r3) : "r"(addr))

#define LDSM_X4_T(r0, r1, r2, r3, addr) \
    asm volatile("ldmatrix.sync.aligned.m8n8.x4.trans.shared.b16 {%0,%1,%2,%3}, [%4];" \
                 : "=r"(r0), "=r"(r1), "=r"(r2), "=r"(r3) : "r"(addr))

#define MMA16816(d, a, b) \
    asm volatile("mma.sync.aligned.m16n8k16.row.col.f32.bf16.bf16.f32 " \
                 "{%0,%1,%2,%3}, {%4,%5,%6,%7}, {%8,%9}, {%0,%1,%2,%3};" \
                 : "+f"((d)[0]), "+f"((d)[1]), "+f"((d)[2]), "+f"((d)[3]) \
                 : "r"((a)[0]), "r"((a)[1]), "r"((a)[2]), "r"((a)[3]), \
                   "r"((b)[0]), "r"((b)[1]))

#define CP_ASYNC16(s, g) \
    asm volatile("cp.async.cg.shared.global [%0], [%1], 16;" :: "r"(s), "l"(g))
#define CP_COMMIT() asm volatile("cp.async.commit_group;" ::: "memory")
#define CP_WAIT0()  asm volatile("cp.async.wait_group 0;" ::: "memory")

__device__ __forceinline__ uint32_t pack_bf16(float a, float b) {
    __nv_bfloat162 t = __halves2bfloat162(__float2bfloat16(a), __float2bfloat16(b));
    return *(uint32_t*)&t;
}

extern __shared__ char dyn_sm[];

// ---------------------------------------------------------------------------
// prep_x / prep_w
// ---------------------------------------------------------------------------
__global__ __launch_bounds__(256) void prep_x(const float* __restrict__ x)
{
    size_t i = (size_t)blockIdx.x * blockDim.x + threadIdx.x;
    float4 v = ((const float4*)x)[i];
    __nv_bfloat16 h0 = __float2bfloat16(v.x);
    __nv_bfloat16 h1 = __float2bfloat16(v.y);
    __nv_bfloat16 h2 = __float2bfloat16(v.z);
    __nv_bfloat16 h3 = __float2bfloat16(v.w);
    __nv_bfloat16 l0 = __float2bfloat16(v.x - __bfloat162float(h0));
    __nv_bfloat16 l1 = __float2bfloat16(v.y - __bfloat162float(h1));
    __nv_bfloat16 l2 = __float2bfloat16(v.z - __bfloat162float(h2));
    __nv_bfloat16 l3 = __float2bfloat16(v.w - __bfloat162float(h3));
    __nv_bfloat162* xh2 = (__nv_bfloat162*)g_xh;
    __nv_bfloat162* xl2 = (__nv_bfloat162*)g_xl;
    xh2[2*i]   = __halves2bfloat162(h0, h1);
    xh2[2*i+1] = __halves2bfloat162(h2, h3);
    xl2[2*i]   = __halves2bfloat162(l0, l1);
    xl2[2*i+1] = __halves2bfloat162(l2, l3);
}

__global__ __launch_bounds__(256) void prep_w(const float* __restrict__ Wq,
                                              const float* __restrict__ Wk,
                                              const float* __restrict__ Wv)
{
    int idx = blockIdx.x * blockDim.x + threadIdx.x;
    if (idx >= 3 * H_ * D_) return;
    int t = idx / (H_ * D_);
    int r = idx % (H_ * D_);
    int n = r / D_;
    int k = r % D_;
    const float* W = (t == 0) ? Wq : (t == 1) ? Wk : Wv;
    float f = W[(size_t)k * H_ + n];
    __nv_bfloat16 h = __float2bfloat16(f);
    g_wh[idx] = h;
    g_wl[idx] = __float2bfloat16(f - __bfloat162float(h));
}

// ---------------------------------------------------------------------------
// proj_mma: 256 threads, 8 warps (4m x 2n), warp tile 32x64, K-chunk 64,
// double-buffered cp.async. LDSM:MMA = 1:4.
// ---------------------------------------------------------------------------
#define PPR 72
#define PARR (128 * PPR * 2)         // 18432 B per array
#define PST  (4 * PARR)              // stage = Ah, Al, Bh, Bl (73728 B)
#define PSMEM_BYTES (2 * PST)        // 147456 B

__global__ __launch_bounds__(256, 1) void proj_mma()
{
    const uint32_t sb = smem_u32(dyn_sm);
    const int tid  = threadIdx.x;
    const int wid  = tid >> 5;
    const int lane = tid & 31;
    const int wm   = wid >> 1;           // 0..3: A rows [32wm, +32)
    const int wn   = wid & 1;            // 0..1: B rows (out cols) [64wn, +64)
    const int mt0  = blockIdx.x;
    const int tgt  = blockIdx.y;

    const __nv_bfloat16* Ah = g_xh + (size_t)mt0 * 128 * D_;
    const __nv_bfloat16* Al = g_xl + (size_t)mt0 * 128 * D_;
    const __nv_bfloat16* Bh = g_wh + (size_t)tgt * H_ * D_;
    const __nv_bfloat16* Bl = g_wl + (size_t)tgt * H_ * D_;

    const uint32_t a_off = ((uint32_t)(lane & 15) * PPR + (lane >> 4) * 8) * 2;
    const uint32_t aoff0 = (uint32_t)(wm * 32) * PPR * 2 + a_off;
    const uint32_t boffw = (uint32_t)(wn * 64) * PPR * 2 + a_off;

    float acc[2][8][4];
#pragma unroll
    for (int i = 0; i < 2; i++)
#pragma unroll
        for (int j = 0; j < 8; j++)
#pragma unroll
            for (int q = 0; q < 4; q++) acc[i][j][q] = 0.f;

    // Prologue: prefetch chunk 0 into stage 0.
    // 4 arrays x 128 rows x 8 c16 = 4096 chunks / 256 thr = 16 each.
    {
#pragma unroll
        for (int it = 0; it < 16; it++) {
            int idx = tid + it * 256;
            int arr = idx >> 10;
            int rem = idx & 1023;
            int row = rem >> 3;
            int c16 = rem & 7;
            const __nv_bfloat16* src =
                (arr == 0) ? Ah : (arr == 1) ? Al : (arr == 2) ? Bh : Bl;
            uint32_t s = sb + arr * PARR + (row * PPR + c16 * 8) * 2;
            CP_ASYNC16(s, src + (size_t)row * D_ + c16 * 8);
        }
        CP_COMMIT();
    }

    for (int c = 0; c < D_ / 64; c++) {
        const int st = c & 1;
        CP_WAIT0();
        __syncthreads();

        if (c + 1 < D_ / 64) {
            const int kc = (c + 1) * 64;
            const uint32_t stb = ((c + 1) & 1) * PST;
#pragma unroll
            for (int it = 0; it < 16; it++) {
                int idx = tid + it * 256;
                int arr = idx >> 10;
                int rem = idx & 1023;
                int row = rem >> 3;
                int c16 = rem & 7;
                const __nv_bfloat16* src =
                    (arr == 0) ? Ah : (arr == 1) ? Al : (arr == 2) ? Bh : Bl;
                uint32_t s = sb + stb + arr * PARR + (row * PPR + c16 * 8) * 2;
                CP_ASYNC16(s, src + (size_t)row * D_ + kc + c16 * 8);
            }
            CP_COMMIT();
        }

        const uint32_t uAh = sb + st * PST;
        const uint32_t uAl = uAh + PARR;
        const uint32_t uBh = uAh + 2 * PARR;
        const uint32_t uBl = uAh + 3 * PARR;

#pragma unroll
        for (int ks = 0; ks < 4; ks++) {
            const uint32_t kb = ks * 16 * 2;
            uint32_t ah[2][4], al[2][4];
            LDSM_X4(ah[0][0], ah[0][1], ah[0][2], ah[0][3], uAh + aoff0 + kb);
            LDSM_X4(ah[1][0], ah[1][1], ah[1][2], ah[1][3], uAh + aoff0 + 16 * PPR * 2 + kb);
            LDSM_X4(al[0][0], al[0][1], al[0][2], al[0][3], uAl + aoff0 + kb);
            LDSM_X4(al[1][0], al[1][1], al[1][2], al[1][3], uAl + aoff0 + 16 * PPR * 2 + kb);

#pragma unroll
            for (int g = 0; g < 2; g++) {     // two groups of 4 n8 frags (32 cols)
                const uint32_t gb = boffw + g * 32 * PPR * 2 + kb;
                uint32_t bh[4][2], bl[4][2];
                uint32_t t0, t1, t2, t3;
                LDSM_X4(t0, t1, t2, t3, uBh + gb);
                bh[0][0] = t0; bh[0][1] = t2; bh[1][0] = t1; bh[1][1] = t3;
                LDSM_X4(t0, t1, t2, t3, uBh + gb + 16 * PPR * 2);
                bh[2][0] = t0; bh[2][1] = t2; bh[3][0] = t1; bh[3][1] = t3;
                LDSM_X4(t0, t1, t2, t3, uBl + gb);
                bl[0][0] = t0; bl[0][1] = t2; bl[1][0] = t1; bl[1][1] = t3;
                LDSM_X4(t0, t1, t2, t3, uBl + gb + 16 * PPR * 2);
                bl[2][0] = t0; bl[2][1] = t2; bl[3][0] = t1; bl[3][1] = t3;

#pragma unroll
                for (int mi = 0; mi < 2; mi++)
#pragma unroll
                    for (int ni = 0; ni < 4; ni++) {
                        MMA16816(acc[mi][g * 4 + ni], ah[mi], bh[ni]);
                        MMA16816(acc[mi][g * 4 + ni], al[mi], bh[ni]);
                        MMA16816(acc[mi][g * 4 + ni], ah[mi], bl[ni]);
                    }
            }
        }
    }

    __nv_bfloat16 *oh, *ol;
    if (tgt == 0)      { oh = g_qh; ol = g_ql; }
    else if (tgt == 1) { oh = g_kh; ol = g_kl; }
    else               { oh = g_vh; ol = g_vl; }
    const float scale = (tgt == 0) ? 0.08838834764831845f : 1.0f;

    const int r0 = mt0 * 128 + wm * 32 + (lane >> 2);
    const int c0 = wn * 64 + (lane & 3) * 2;
#pragma unroll
    for (int mi = 0; mi < 2; mi++)
#pragma unroll
        for (int ni = 0; ni < 8; ni++) {
            int cc = c0 + ni * 8;
#pragma unroll
            for (int hh = 0; hh < 2; hh++) {
                int rr = r0 + mi * 16 + hh * 8;
                float v0 = acc[mi][ni][2*hh + 0] * scale;
                float v1 = acc[mi][ni][2*hh + 1] * scale;
                __nv_bfloat16 h0 = __float2bfloat16(v0);
                __nv_bfloat16 h1 = __float2bfloat16(v1);
                __nv_bfloat16 l0 = __float2bfloat16(v0 - __bfloat162float(h0));
                __nv_bfloat16 l1 = __float2bfloat16(v1 - __bfloat162float(h1));
                *(__nv_bfloat162*)&oh[(size_t)rr * H_ + cc] = __halves2bfloat162(h0, h1);
                *(__nv_bfloat162*)&ol[(size_t)rr * H_ + cc] = __halves2bfloat162(l0, l1);
            }
        }
}

// ---------------------------------------------------------------------------
// attn_part: 4-way split-KV causal flash attention partial. (R10-proven)
// ---------------------------------------------------------------------------
#define QP 136
#define KP 136
#define QARR (128 * QP * 2)
#define KARR (64 * KP * 2)
#define OFF_QH 0
#define OFF_QL QARR
#define OFF_STG (2 * QARR)
#define STG_SZ (4 * KARR)
#define ATTN_SMEM (OFF_STG + 2 * STG_SZ)

__global__ __launch_bounds__(256, 1) void attn_part()
{
    char* smc = dyn_sm;
    const uint32_t sb = smem_u32(smc);
    const int tid  = threadIdx.x;
    const int w    = tid >> 5;
    const int lane = tid & 31;

    const int i    = blockIdx.x;
    const int qt   = 31 - (i >> 4);
    const int b    = (i >> 2) & 3;
    const int j    = i & 3;
    const int q0   = qt * 128;
    const int ntot = 2 * qt + 2;
    const int kt0  = (j * ntot) >> 2;
    const int kt1  = ((j + 1) * ntot) >> 2;
    const size_t gbase = (size_t)b * T_ * H_;

    const uint32_t lrow  = (lane & 15);
    const uint32_t lcol8 = (lane >> 4) * 8;
    const int rA = (lane >> 2);
    const int cq = (lane & 3) * 2;

    float O[16][4];
#pragma unroll
    for (int n = 0; n < 16; n++)
#pragma unroll
        for (int q = 0; q < 4; q++) O[n][q] = 0.f;
    float mA = -1e30f, mB = -1e30f, lA = 0.f, lB = 0.f;

    if (kt0 < kt1) {
        {
            const size_t g0 = gbase + (size_t)q0 * H_;
#pragma unroll
            for (int it = 0; it < 8; it++) {
                int idx = tid + it * 256;
                int row = idx >> 4;
                int c8  = idx & 15;
                size_t g = g0 + (size_t)row * H_ + c8 * 8;
                int so = (row * QP + c8 * 8) * 2;
                *(uint4*)(smc + OFF_QH + so) = *(const uint4*)&g_qh[g];
                *(uint4*)(smc + OFF_QL + so) = *(const uint4*)&g_ql[g];
            }
        }

        {
            const int k0 = kt0 * 64;
            const int st = kt0 & 1;
#pragma unroll
            for (int it = 0; it < 16; it++) {
                int idx = tid + it * 256;
                int arr = idx >> 10;
                int row = (idx >> 4) & 63;
                int c8  = idx & 15;
                const __nv_bfloat16* src =
                    (arr == 0) ? g_kh : (arr == 1) ? g_kl : (arr == 2) ? g_vh : g_vl;
                uint32_t s = sb + OFF_STG + st * STG_SZ + arr * KARR + (row * KP + c8 * 8) * 2;
                CP_ASYNC16(s, src + gbase + (size_t)(k0 + row) * H_ + c8 * 8);
            }
            CP_COMMIT();
        }

        for (int kt = kt0; kt < kt1; kt++) {
            const int st = kt & 1;
            const uint32_t stK = sb + OFF_STG + st * STG_SZ;
            CP_WAIT0();
            __syncthreads();

            if (kt + 1 < kt1) {
                const int k0n = (kt + 1) * 64;
                const int stn = (kt + 1) & 1;
#pragma unroll
                for (int it = 0; it < 16; it++) {
                    int idx = tid + it * 256;
                    int arr = idx >> 10;
                    int row = (idx >> 4) & 63;
                    int c8  = idx & 15;
                    const __nv_bfloat16* src =
                        (arr == 0) ? g_kh : (arr == 1) ? g_kl : (arr == 2) ? g_vh : g_vl;
                    uint32_t s = sb + OFF_STG + stn * STG_SZ + arr * KARR + (row * KP + c8 * 8) * 2;
                    CP_ASYNC16(s, src + gbase + (size_t)(k0n + row) * H_ + c8 * 8);
                }
                CP_COMMIT();
            }

            const int k0 = kt * 64;

            float accS[8][4];
#pragma unroll
            for (int n = 0; n < 8; n++)
#pragma unroll
                for (int q = 0; q < 4; q++) accS[n][q] = 0.f;

#pragma unroll
            for (int ks = 0; ks < 8; ks++) {
                uint32_t ah[4], al[4], bh[8][2], bl[8][2];
                uint32_t aQ = sb + OFF_QH + (((16 * w + lrow) * QP) + lcol8 + ks * 16) * 2;
                LDSM_X4(ah[0], ah[1], ah[2], ah[3], aQ);
                LDSM_X4(al[0], al[1], al[2], al[3], aQ + (OFF_QL - OFF_QH));
                uint32_t t0, t1, t2, t3;
#pragma unroll
                for (int nj = 0; nj < 4; nj++) {
                    uint32_t aK = stK + (((nj * 16 + lrow) * KP) + lcol8 + ks * 16) * 2;
                    LDSM_X4(t0, t1, t2, t3, aK);
                    bh[2*nj][0] = t0; bh[2*nj][1] = t2;
                    bh[2*nj+1][0] = t1; bh[2*nj+1][1] = t3;
                    LDSM_X4(t0, t1, t2, t3, aK + KARR);
                    bl[2*nj][0] = t0; bl[2*nj][1] = t2;
                    bl[2*nj+1][0] = t1; bl[2*nj+1][1] = t3;
                }
#pragma unroll
                for (int n = 0; n < 8; n++) {
                    MMA16816(accS[n], ah, bh[n]);
                    MMA16816(accS[n], al, bh[n]);
                    MMA16816(accS[n], ah, bl[n]);
                }
            }

            if (k0 + 63 > q0 + 16 * w) {
                const int qgA = q0 + 16 * w + rA;
                const int qgB = qgA + 8;
#pragma unroll
                for (int n = 0; n < 8; n++) {
                    int kg0 = k0 + n * 8 + cq;
                    int kg1 = kg0 + 1;
                    if (kg0 > qgA) accS[n][0] = -1e30f;
                    if (kg1 > qgA) accS[n][1] = -1e30f;
                    if (kg0 > qgB) accS[n][2] = -1e30f;
                    if (kg1 > qgB) accS[n][3] = -1e30f;
                }
            }

            float mxA = -1e30f, mxB = -1e30f;
#pragma unroll
            for (int n = 0; n < 8; n++) {
                mxA = fmaxf(mxA, fmaxf(accS[n][0], accS[n][1]));
                mxB = fmaxf(mxB, fmaxf(accS[n][2], accS[n][3]));
            }
            mxA = fmaxf(mxA, __shfl_xor_sync(0xffffffffu, mxA, 1));
            mxA = fmaxf(mxA, __shfl_xor_sync(0xffffffffu, mxA, 2));
            mxB = fmaxf(mxB, __shfl_xor_sync(0xffffffffu, mxB, 1));
            mxB = fmaxf(mxB, __shfl_xor_sync(0xffffffffu, mxB, 2));

            float mAn = fmaxf(mA, mxA);
            float mBn = fmaxf(mB, mxB);
            float aAl = __expf(mA - mAn);
            float aBl = __expf(mB - mBn);
            mA = mAn; mB = mBn;

            float sA = 0.f, sB = 0.f;
#pragma unroll
            for (int n = 0; n < 8; n++) {
                accS[n][0] = __expf(accS[n][0] - mAn);
                accS[n][1] = __expf(accS[n][1] - mAn);
                accS[n][2] = __expf(accS[n][2] - mBn);
                accS[n][3] = __expf(accS[n][3] - mBn);
                sA += accS[n][0] + accS[n][1];
                sB += accS[n][2] + accS[n][3];
            }
            sA += __shfl_xor_sync(0xffffffffu, sA, 1);
            sA += __shfl_xor_sync(0xffffffffu, sA, 2);
            sB += __shfl_xor_sync(0xffffffffu, sB, 1);
            sB += __shfl_xor_sync(0xffffffffu, sB, 2);
            lA = lA * aAl + sA;
            lB = lB * aBl + sB;

#pragma unroll
            for (int n = 0; n < 16; n++) {
                O[n][0] *= aAl; O[n][1] *= aAl;
                O[n][2] *= aBl; O[n][3] *= aBl;
            }

            const uint32_t stV = stK + 2 * KARR;
#pragma unroll
            for (int ks = 0; ks < 4; ks++) {
                uint32_t ph[4], pl[4];
                {
                    const int j0 = 2 * ks, j1 = 2 * ks + 1;
                    float p00 = accS[j0][0], p01 = accS[j0][1];
                    float p02 = accS[j0][2], p03 = accS[j0][3];
                    float p10 = accS[j1][0], p11 = accS[j1][1];
                    float p12 = accS[j1][2], p13 = accS[j1][3];
                    ph[0] = pack_bf16(p00, p01);
                    ph[1] = pack_bf16(p02, p03);
                    ph[2] = pack_bf16(p10, p11);
                    ph[3] = pack_bf16(p12, p13);
                    __nv_bfloat162* h;
                    h = (__nv_bfloat162*)&ph[0];
                    pl[0] = pack_bf16(p00 - __bfloat162float(h->x), p01 - __bfloat162float(h->y));
                    h = (__nv_bfloat162*)&ph[1];
                    pl[1] = pack_bf16(p02 - __bfloat162float(h->x), p03 - __bfloat162float(h->y));
                    h = (__nv_bfloat162*)&ph[2];
                    pl[2] = pack_bf16(p10 - __bfloat162float(h->x), p11 - __bfloat162float(h->y));
                    h = (__nv_bfloat162*)&ph[3];
                    pl[3] = pack_bf16(p12 - __bfloat162float(h->x), p13 - __bfloat162float(h->y));
                }

                uint32_t vh[16][2], vl[16][2];
                uint32_t t0, t1, t2, t3;
#pragma unroll
                for (int nj = 0; nj < 8; nj++) {
                    uint32_t aV = stV + (((ks * 16 + lrow) * KP) + nj * 16 + lcol8) * 2;
                    LDSM_X4_T(t0, t1, t2, t3, aV);
                    vh[2*nj][0] = t0; vh[2*nj][1] = t1;
                    vh[2*nj+1][0] = t2; vh[2*nj+1][1] = t3;
                    LDSM_X4_T(t0, t1, t2, t3, aV + KARR);
                    vl[2*nj][0] = t0; vl[2*nj][1] = t1;
                    vl[2*nj+1][0] = t2; vl[2*nj+1][1] = t3;
                }
#pragma unroll
                for (int n = 0; n < 16; n++) {
                    MMA16816(O[n], ph, vh[n]);
                    MMA16816(O[n], pl, vh[n]);
                    MMA16816(O[n], ph, vl[n]);
                }
            }
        }
    }

    float* po = g_po + (size_t)j * M_TOT * H_;
    const int rowA = q0 + 16 * w + rA;
    const size_t grA = (size_t)b * T_ + rowA;
#pragma unroll
    for (int n = 0; n < 16; n++) {
        int col = n * 8 + cq;
        *(float2*)&po[grA * H_ + col]       = make_float2(O[n][0], O[n][1]);
        *(float2*)&po[(grA + 8) * H_ + col] = make_float2(O[n][2], O[n][3]);
    }
    if ((lane & 3) == 0) {
        g_pm[(size_t)j * M_TOT + grA]     = mA;
        g_pm[(size_t)j * M_TOT + grA + 8] = mB;
        g_pl[(size_t)j * M_TOT + grA]     = lA;
        g_pl[(size_t)j * M_TOT + grA + 8] = lB;
    }
}

// ---------------------------------------------------------------------------
// attn_merge: combine NSPLIT partials.
// ---------------------------------------------------------------------------
__global__ __launch_bounds__(256) void attn_merge(float* __restrict__ out)
{
    size_t idx = (size_t)blockIdx.x * 256 + threadIdx.x;
    size_t row = idx >> 5;
    int c4 = (int)(idx & 31) * 4;

    float mv[NSPLIT], lv[NSPLIT];
    float m = -1e30f;
#pragma unroll
    for (int j = 0; j < NSPLIT; j++) {
        mv[j] = g_pm[(size_t)j * M_TOT + row];
        lv[j] = g_pl[(size_t)j * M_TOT + row];
        m = fmaxf(m, mv[j]);
    }
    float wsum = 0.f;
    float wv[NSPLIT];
#pragma unroll
    for (int j = 0; j < NSPLIT; j++) {
        wv[j] = __expf(mv[j] - m);
        wsum += wv[j] * lv[j];
    }
    float inv = 1.f / wsum;

    float4 o = make_float4(0.f, 0.f, 0.f, 0.f);
#pragma unroll
    for (int j = 0; j < NSPLIT; j++) {
        float4 a = *(float4*)&g_po[(size_t)j * M_TOT * H_ + row * H_ + c4];
        o.x += wv[j] * a.x;
        o.y += wv[j] * a.y;
        o.z += wv[j] * a.z;
        o.w += wv[j] * a.w;
    }
    o.x *= inv; o.y *= inv; o.z *= inv; o.w *= inv;
    *(float4*)&out[row * H_ + c4] = o;
}

// ---------------------------------------------------------------------------
extern "C" void kernel_launch(void* const* d_in, const int* in_sizes, int n_in,
                              void* d_out, int out_size)
{
    const float* x  = (const float*)d_in[0];
    const float* Wq = (const float*)d_in[1];
    const float* Wk = (const float*)d_in[2];
    const float* Wv = (const float*)d_in[3];
    float* out = (float*)d_out;

    prep_x<<<(M_TOT * D_ / 4 + 255) / 256, 256>>>(x);
    prep_w<<<(3 * H_ * D_ + 255) / 256, 256>>>(Wq, Wk, Wv);

    cudaFuncSetAttribute(proj_mma, cudaFuncAttributeMaxDynamicSharedMemorySize,
                         PSMEM_BYTES);
    proj_mma<<<dim3(M_TOT / 128, 3), 256, PSMEM_BYTES>>>();

    cudaFuncSetAttribute(attn_part, cudaFuncAttributeMaxDynamicSharedMemorySize,
                         ATTN_SMEM);
    attn_part<<<32 * B_ * NSPLIT, 256, ATTN_SMEM>>>();

    attn_merge<<<M_TOT * 32 / 256, 256>>>(out);
}

// round 13
// speedup vs baseline: 1.0972x; 1.0972x over previous
#include <cuda_runtime.h>
#include <cuda_bf16.h>
#include <math.h>
#include <stdint.h>

#define B_ 4
#define T_ 4096
#define D_ 2048
#define H_ 128
#define M_TOT (B_*T_)
#define NSPLIT 4

// ---------------- device scratch (no allocations allowed) -------------------
__device__ __nv_bfloat16 g_wh[3 * H_ * D_];
__device__ __nv_bfloat16 g_wl[3 * H_ * D_];
__device__ __nv_bfloat16 g_qh[M_TOT * H_];
__device__ __nv_bfloat16 g_ql[M_TOT * H_];
__device__ __nv_bfloat16 g_kh[M_TOT * H_];
__device__ __nv_bfloat16 g_kl[M_TOT * H_];
__device__ __nv_bfloat16 g_vh[M_TOT * H_];
__device__ __nv_bfloat16 g_vl[M_TOT * H_];
__device__ float g_po[NSPLIT * (size_t)M_TOT * H_];
__device__ float g_pm[NSPLIT * M_TOT];
__device__ float g_pl[NSPLIT * M_TOT];

// ---------------- helpers ---------------------------------------------------
__device__ __forceinline__ uint32_t smem_u32(const void* p) {
    uint32_t a;
    asm("{ .reg .u64 t; cvta.to.shared.u64 t, %1; cvt.u32.u64 %0, t; }" : "=r"(a) : "l"(p));
    return a;
}

#define LDSM_X4(r0, r1, r2, r3, addr) \
    asm volatile("ldmatrix.sync.aligned.m8n8.x4.shared.b16 {%0,%1,%2,%3}, [%4];" \
                 : "=r"(r0), "=r"(r1), "=r"(r2), "=r"(r3) : "r"(addr))

#define LDSM_X4_T(r0, r1, r2, r3, addr) \
    asm volatile("ldmatrix.sync.aligned.m8n8.x4.trans.shared.b16 {%0,%1,%2,%3}, [%4];" \
                 : "=r"(r0), "=r"(r1), "=r"(r2), "=r"(r3) : "r"(addr))

#define MMA16816(d, a, b) \
    asm volatile("mma.sync.aligned.m16n8k16.row.col.f32.bf16.bf16.f32 " \
                 "{%0,%1,%2,%3}, {%4,%5,%6,%7}, {%8,%9}, {%0,%1,%2,%3};" \
                 : "+f"((d)[0]), "+f"((d)[1]), "+f"((d)[2]), "+f"((d)[3]) \
                 : "r"((a)[0]), "r"((a)[1]), "r"((a)[2]), "r"((a)[3]), \
                   "r"((b)[0]), "r"((b)[1]))

#define CP_ASYNC16(s, g) \
    asm volatile("cp.async.cg.shared.global [%0], [%1], 16;" :: "r"(s), "l"(g))
#define CP_COMMIT() asm volatile("cp.async.commit_group;" ::: "memory")
#define CP_WAIT0()  asm volatile("cp.async.wait_group 0;" ::: "memory")

__device__ __forceinline__ uint32_t pack_bf16(float a, float b) {
    __nv_bfloat162 t = __halves2bfloat162(__float2bfloat16(a), __float2bfloat16(b));
    return *(uint32_t*)&t;
}

extern __shared__ char dyn_sm[];

// ---------------------------------------------------------------------------
// prep_w: transpose W[D,H] -> [H,D] with bf16 hi/lo split
// ---------------------------------------------------------------------------
__global__ __launch_bounds__(256) void prep_w(const float* __restrict__ Wq,
                                              const float* __restrict__ Wk,
                                              const float* __restrict__ Wv)
{
    int idx = blockIdx.x * blockDim.x + threadIdx.x;
    if (idx >= 3 * H_ * D_) return;
    int t = idx / (H_ * D_);
    int r = idx % (H_ * D_);
    int n = r / D_;
    int k = r % D_;
    const float* W = (t == 0) ? Wq : (t == 1) ? Wk : Wv;
    float f = W[(size_t)k * H_ + n];
    __nv_bfloat16 h = __float2bfloat16(f);
    g_wh[idx] = h;
    g_wl[idx] = __float2bfloat16(f - __bfloat162float(h));
}

// ---------------------------------------------------------------------------
// proj_mma: fused x-split GEMM. 256 threads, 8 warps (4m x 2n), K-chunk 64.
// x fp32 loaded via LDG into regs (issued one chunk ahead), converted to
// bf16 hi/lo in-kernel (single-buffered A smem); B double-buffered cp.async.
// ---------------------------------------------------------------------------
#define PPR 72
#define PARR_A (128 * PPR * 2)          // 18432 B per A array
#define OFF_AH 0
#define OFF_AL PARR_A
#define OFF_B  (2 * PARR_A)             // 36864
#define BARR   (128 * PPR * 2)          // 18432 B per B array
#define BST    (2 * BARR)               // stage: Bh, Bl = 36864
#define PSMEM_BYTES (2 * PARR_A + 2 * BST)   // 110592 B

__global__ __launch_bounds__(256, 1) void proj_mma(const float* __restrict__ x)
{
    const uint32_t sb = smem_u32(dyn_sm);
    const int tid  = threadIdx.x;
    const int wid  = tid >> 5;
    const int lane = tid & 31;
    const int wm   = wid >> 1;           // 0..3: A rows [32wm, +32)
    const int wn   = wid & 1;            // 0..1: out cols [64wn, +64)
    const int mt0  = blockIdx.x;
    const int tgt  = blockIdx.y;

    const float* Xt = x + (size_t)mt0 * 128 * D_;
    const __nv_bfloat16* Bh = g_wh + (size_t)tgt * H_ * D_;
    const __nv_bfloat16* Bl = g_wl + (size_t)tgt * H_ * D_;

    const uint32_t a_off = ((uint32_t)(lane & 15) * PPR + (lane >> 4) * 8) * 2;
    const uint32_t aoffH = OFF_AH + (uint32_t)(wm * 32) * PPR * 2 + a_off;
    const uint32_t boffw = (uint32_t)(wn * 64) * PPR * 2 + a_off;

    // Per-thread x staging: 8 float4 (row = idx>>4, c4 = (idx&15)*4).
    const int xrow[1] = {0};  (void)xrow;

    float acc[2][8][4];
#pragma unroll
    for (int i = 0; i < 2; i++)
#pragma unroll
        for (int j = 0; j < 8; j++)
#pragma unroll
            for (int q = 0; q < 4; q++) acc[i][j][q] = 0.f;

    float4 xs[8];

    // ---- Prologue: x chunk 0 -> regs; B chunk 0 -> stage 0; convert chunk 0.
#pragma unroll
    for (int it = 0; it < 8; it++) {
        int idx = tid + it * 256;
        int row = idx >> 4;
        int c4  = idx & 15;
        xs[it] = *(const float4*)&Xt[(size_t)row * D_ + c4 * 4];
    }
#pragma unroll
    for (int it = 0; it < 8; it++) {
        int idx = tid + it * 256;          // 0..2047 16B chunks
        int arr = idx >> 10;               // 0=Bh 1=Bl
        int rem = idx & 1023;
        int row = rem >> 3;
        int c16 = rem & 7;
        const __nv_bfloat16* src = arr ? Bl : Bh;
        uint32_t s = sb + OFF_B + arr * BARR + (row * PPR + c16 * 8) * 2;
        CP_ASYNC16(s, src + (size_t)row * D_ + c16 * 8);
    }
    CP_COMMIT();
    // convert chunk 0 -> A smem
#pragma unroll
    for (int it = 0; it < 8; it++) {
        int idx = tid + it * 256;
        int row = idx >> 4;
        int c4  = (idx & 15) * 4;
        float4 v = xs[it];
        uint32_t h0 = pack_bf16(v.x, v.y);
        uint32_t h1 = pack_bf16(v.z, v.w);
        __nv_bfloat162 hh0 = *(__nv_bfloat162*)&h0;
        __nv_bfloat162 hh1 = *(__nv_bfloat162*)&h1;
        uint32_t l0 = pack_bf16(v.x - __bfloat162float(hh0.x), v.y - __bfloat162float(hh0.y));
        uint32_t l1 = pack_bf16(v.z - __bfloat162float(hh1.x), v.w - __bfloat162float(hh1.y));
        uint2 hv; hv.x = h0; hv.y = h1;
        uint2 lv; lv.x = l0; lv.y = l1;
        *(uint2*)(dyn_sm + OFF_AH + (row * PPR + c4) * 2) = hv;
        *(uint2*)(dyn_sm + OFF_AL + (row * PPR + c4) * 2) = lv;
    }

    for (int c = 0; c < D_ / 64; c++) {
        const int st = c & 1;
        // Issue x loads for chunk c+1 early (covered by MMA phase).
        if (c + 1 < D_ / 64) {
            const int kc = (c + 1) * 64;
#pragma unroll
            for (int it = 0; it < 8; it++) {
                int idx = tid + it * 256;
                int row = idx >> 4;
                int c4  = idx & 15;
                xs[it] = *(const float4*)&Xt[(size_t)row * D_ + kc + c4 * 4];
            }
        }
        CP_WAIT0();
        __syncthreads();   // B(c) ready; A(c) stores visible; prior MMAs done

        if (c + 1 < D_ / 64) {
            const int kc = (c + 1) * 64;
            const uint32_t stb = ((c + 1) & 1) * BST;
#pragma unroll
            for (int it = 0; it < 8; it++) {
                int idx = tid + it * 256;
                int arr = idx >> 10;
                int rem = idx & 1023;
                int row = rem >> 3;
                int c16 = rem & 7;
                const __nv_bfloat16* src = arr ? Bl : Bh;
                uint32_t s = sb + OFF_B + stb + arr * BARR + (row * PPR + c16 * 8) * 2;
                CP_ASYNC16(s, src + (size_t)row * D_ + kc + c16 * 8);
            }
            CP_COMMIT();
        }

        const uint32_t uAh = sb + OFF_AH;
        const uint32_t uAl = sb + OFF_AL;
        const uint32_t uBh = sb + OFF_B + st * BST;
        const uint32_t uBl = uBh + BARR;

#pragma unroll
        for (int ks = 0; ks < 4; ks++) {
            const uint32_t kb = ks * 16 * 2;
            uint32_t ah[2][4], al[2][4];
            LDSM_X4(ah[0][0], ah[0][1], ah[0][2], ah[0][3], uAh + aoffH + kb);
            LDSM_X4(ah[1][0], ah[1][1], ah[1][2], ah[1][3], uAh + aoffH + 16 * PPR * 2 + kb);
            LDSM_X4(al[0][0], al[0][1], al[0][2], al[0][3], uAl + aoffH + kb);
            LDSM_X4(al[1][0], al[1][1], al[1][2], al[1][3], uAl + aoffH + 16 * PPR * 2 + kb);

#pragma unroll
            for (int g = 0; g < 2; g++) {
                const uint32_t gb = boffw + g * 32 * PPR * 2 + kb;
                uint32_t bh[4][2], bl[4][2];
                uint32_t t0, t1, t2, t3;
                LDSM_X4(t0, t1, t2, t3, uBh + gb);
                bh[0][0] = t0; bh[0][1] = t2; bh[1][0] = t1; bh[1][1] = t3;
                LDSM_X4(t0, t1, t2, t3, uBh + gb + 16 * PPR * 2);
                bh[2][0] = t0; bh[2][1] = t2; bh[3][0] = t1; bh[3][1] = t3;
                LDSM_X4(t0, t1, t2, t3, uBl + gb);
                bl[0][0] = t0; bl[0][1] = t2; bl[1][0] = t1; bl[1][1] = t3;
                LDSM_X4(t0, t1, t2, t3, uBl + gb + 16 * PPR * 2);
                bl[2][0] = t0; bl[2][1] = t2; bl[3][0] = t1; bl[3][1] = t3;

#pragma unroll
                for (int mi = 0; mi < 2; mi++)
#pragma unroll
                    for (int ni = 0; ni < 4; ni++) {
                        MMA16816(acc[mi][g * 4 + ni], ah[mi], bh[ni]);
                        MMA16816(acc[mi][g * 4 + ni], al[mi], bh[ni]);
                        MMA16816(acc[mi][g * 4 + ni], ah[mi], bl[ni]);
                    }
            }
        }
        __syncthreads();   // everyone done reading A(c) before overwrite

        if (c + 1 < D_ / 64) {
#pragma unroll
            for (int it = 0; it < 8; it++) {
                int idx = tid + it * 256;
                int row = idx >> 4;
                int c4  = (idx & 15) * 4;
                float4 v = xs[it];
                uint32_t h0 = pack_bf16(v.x, v.y);
                uint32_t h1 = pack_bf16(v.z, v.w);
                __nv_bfloat162 hh0 = *(__nv_bfloat162*)&h0;
                __nv_bfloat162 hh1 = *(__nv_bfloat162*)&h1;
                uint32_t l0 = pack_bf16(v.x - __bfloat162float(hh0.x), v.y - __bfloat162float(hh0.y));
                uint32_t l1 = pack_bf16(v.z - __bfloat162float(hh1.x), v.w - __bfloat162float(hh1.y));
                uint2 hv; hv.x = h0; hv.y = h1;
                uint2 lv; lv.x = l0; lv.y = l1;
                *(uint2*)(dyn_sm + OFF_AH + (row * PPR + c4) * 2) = hv;
                *(uint2*)(dyn_sm + OFF_AL + (row * PPR + c4) * 2) = lv;
            }
        }
    }

    __nv_bfloat16 *oh, *ol;
    if (tgt == 0)      { oh = g_qh; ol = g_ql; }
    else if (tgt == 1) { oh = g_kh; ol = g_kl; }
    else               { oh = g_vh; ol = g_vl; }
    const float scale = (tgt == 0) ? 0.08838834764831845f : 1.0f;

    const int r0 = mt0 * 128 + wm * 32 + (lane >> 2);
    const int c0 = wn * 64 + (lane & 3) * 2;
#pragma unroll
    for (int mi = 0; mi < 2; mi++)
#pragma unroll
        for (int ni = 0; ni < 8; ni++) {
            int cc = c0 + ni * 8;
#pragma unroll
            for (int hh = 0; hh < 2; hh++) {
                int rr = r0 + mi * 16 + hh * 8;
                float v0 = acc[mi][ni][2*hh + 0] * scale;
                float v1 = acc[mi][ni][2*hh + 1] * scale;
                __nv_bfloat16 h0 = __float2bfloat16(v0);
                __nv_bfloat16 h1 = __float2bfloat16(v1);
                __nv_bfloat16 l0 = __float2bfloat16(v0 - __bfloat162float(h0));
                __nv_bfloat16 l1 = __float2bfloat16(v1 - __bfloat162float(h1));
                *(__nv_bfloat162*)&oh[(size_t)rr * H_ + cc] = __halves2bfloat162(h0, h1);
                *(__nv_bfloat162*)&ol[(size_t)rr * H_ + cc] = __halves2bfloat162(l0, l1);
            }
        }
}

// ---------------------------------------------------------------------------
// attn_part: 4-way split-KV causal flash attention partial. (R10-proven)
// ---------------------------------------------------------------------------
#define QP 136
#define KP 136
#define QARR (128 * QP * 2)
#define KARR (64 * KP * 2)
#define OFF_QH 0
#define OFF_QL QARR
#define OFF_STG (2 * QARR)
#define STG_SZ (4 * KARR)
#define ATTN_SMEM (OFF_STG + 2 * STG_SZ)

__global__ __launch_bounds__(256, 1) void attn_part()
{
    char* smc = dyn_sm;
    const uint32_t sb = smem_u32(smc);
    const int tid  = threadIdx.x;
    const int w    = tid >> 5;
    const int lane = tid & 31;

    const int i    = blockIdx.x;
    const int qt   = 31 - (i >> 4);
    const int b    = (i >> 2) & 3;
    const int j    = i & 3;
    const int q0   = qt * 128;
    const int ntot = 2 * qt + 2;
    const int kt0  = (j * ntot) >> 2;
    const int kt1  = ((j + 1) * ntot) >> 2;
    const size_t gbase = (size_t)b * T_ * H_;

    const uint32_t lrow  = (lane & 15);
    const uint32_t lcol8 = (lane >> 4) * 8;
    const int rA = (lane >> 2);
    const int cq = (lane & 3) * 2;

    float O[16][4];
#pragma unroll
    for (int n = 0; n < 16; n++)
#pragma unroll
        for (int q = 0; q < 4; q++) O[n][q] = 0.f;
    float mA = -1e30f, mB = -1e30f, lA = 0.f, lB = 0.f;

    if (kt0 < kt1) {
        {
            const size_t g0 = gbase + (size_t)q0 * H_;
#pragma unroll
            for (int it = 0; it < 8; it++) {
                int idx = tid + it * 256;
                int row = idx >> 4;
                int c8  = idx & 15;
                size_t g = g0 + (size_t)row * H_ + c8 * 8;
                int so = (row * QP + c8 * 8) * 2;
                *(uint4*)(smc + OFF_QH + so) = *(const uint4*)&g_qh[g];
                *(uint4*)(smc + OFF_QL + so) = *(const uint4*)&g_ql[g];
            }
        }

        {
            const int k0 = kt0 * 64;
            const int st = kt0 & 1;
#pragma unroll
            for (int it = 0; it < 16; it++) {
                int idx = tid + it * 256;
                int arr = idx >> 10;
                int row = (idx >> 4) & 63;
                int c8  = idx & 15;
                const __nv_bfloat16* src =
                    (arr == 0) ? g_kh : (arr == 1) ? g_kl : (arr == 2) ? g_vh : g_vl;
                uint32_t s = sb + OFF_STG + st * STG_SZ + arr * KARR + (row * KP + c8 * 8) * 2;
                CP_ASYNC16(s, src + gbase + (size_t)(k0 + row) * H_ + c8 * 8);
            }
            CP_COMMIT();
        }

        for (int kt = kt0; kt < kt1; kt++) {
            const int st = kt & 1;
            const uint32_t stK = sb + OFF_STG + st * STG_SZ;
            CP_WAIT0();
            __syncthreads();

            if (kt + 1 < kt1) {
                const int k0n = (kt + 1) * 64;
                const int stn = (kt + 1) & 1;
#pragma unroll
                for (int it = 0; it < 16; it++) {
                    int idx = tid + it * 256;
                    int arr = idx >> 10;
                    int row = (idx >> 4) & 63;
                    int c8  = idx & 15;
                    const __nv_bfloat16* src =
                        (arr == 0) ? g_kh : (arr == 1) ? g_kl : (arr == 2) ? g_vh : g_vl;
                    uint32_t s = sb + OFF_STG + stn * STG_SZ + arr * KARR + (row * KP + c8 * 8) * 2;
                    CP_ASYNC16(s, src + gbase + (size_t)(k0n + row) * H_ + c8 * 8);
                }
                CP_COMMIT();
            }

            const int k0 = kt * 64;

            float accS[8][4];
#pragma unroll
            for (int n = 0; n < 8; n++)
#pragma unroll
                for (int q = 0; q < 4; q++) accS[n][q] = 0.f;

#pragma unroll
            for (int ks = 0; ks < 8; ks++) {
                uint32_t ah[4], al[4], bh[8][2], bl[8][2];
                uint32_t aQ = sb + OFF_QH + (((16 * w + lrow) * QP) + lcol8 + ks * 16) * 2;
                LDSM_X4(ah[0], ah[1], ah[2], ah[3], aQ);
                LDSM_X4(al[0], al[1], al[2], al[3], aQ + (OFF_QL - OFF_QH));
                uint32_t t0, t1, t2, t3;
#pragma unroll
                for (int nj = 0; nj < 4; nj++) {
                    uint32_t aK = stK + (((nj * 16 + lrow) * KP) + lcol8 + ks * 16) * 2;
                    LDSM_X4(t0, t1, t2, t3, aK);
                    bh[2*nj][0] = t0; bh[2*nj][1] = t2;
                    bh[2*nj+1][0] = t1; bh[2*nj+1][1] = t3;
                    LDSM_X4(t0, t1, t2, t3, aK + KARR);
                    bl[2*nj][0] = t0; bl[2*nj][1] = t2;
                    bl[2*nj+1][0] = t1; bl[2*nj+1][1] = t3;
                }
#pragma unroll
                for (int n = 0; n < 8; n++) {
                    MMA16816(accS[n], ah, bh[n]);
                    MMA16816(accS[n], al, bh[n]);
                    MMA16816(accS[n], ah, bl[n]);
                }
            }

            if (k0 + 63 > q0 + 16 * w) {
                const int qgA = q0 + 16 * w + rA;
                const int qgB = qgA + 8;
#pragma unroll
                for (int n = 0; n < 8; n++) {
                    int kg0 = k0 + n * 8 + cq;
                    int kg1 = kg0 + 1;
                    if (kg0 > qgA) accS[n][0] = -1e30f;
                    if (kg1 > qgA) accS[n][1] = -1e30f;
                    if (kg0 > qgB) accS[n][2] = -1e30f;
                    if (kg1 > qgB) accS[n][3] = -1e30f;
                }
            }

            float mxA = -1e30f, mxB = -1e30f;
#pragma unroll
            for (int n = 0; n < 8; n++) {
                mxA = fmaxf(mxA, fmaxf(accS[n][0], accS[n][1]));
                mxB = fmaxf(mxB, fmaxf(accS[n][2], accS[n][3]));
            }
            mxA = fmaxf(mxA, __shfl_xor_sync(0xffffffffu, mxA, 1));
            mxA = fmaxf(mxA, __shfl_xor_sync(0xffffffffu, mxA, 2));
            mxB = fmaxf(mxB, __shfl_xor_sync(0xffffffffu, mxB, 1));
            mxB = fmaxf(mxB, __shfl_xor_sync(0xffffffffu, mxB, 2));

            float mAn = fmaxf(mA, mxA);
            float mBn = fmaxf(mB, mxB);
            float aAl = __expf(mA - mAn);
            float aBl = __expf(mB - mBn);
            mA = mAn; mB = mBn;

            float sA = 0.f, sB = 0.f;
#pragma unroll
            for (int n = 0; n < 8; n++) {
                accS[n][0] = __expf(accS[n][0] - mAn);
                accS[n][1] = __expf(accS[n][1] - mAn);
                accS[n][2] = __expf(accS[n][2] - mBn);
                accS[n][3] = __expf(accS[n][3] - mBn);
                sA += accS[n][0] + accS[n][1];
                sB += accS[n][2] + accS[n][3];
            }
            sA += __shfl_xor_sync(0xffffffffu, sA, 1);
            sA += __shfl_xor_sync(0xffffffffu, sA, 2);
            sB += __shfl_xor_sync(0xffffffffu, sB, 1);
            sB += __shfl_xor_sync(0xffffffffu, sB, 2);
            lA = lA * aAl + sA;
            lB = lB * aBl + sB;

#pragma unroll
            for (int n = 0; n < 16; n++) {
                O[n][0] *= aAl; O[n][1] *= aAl;
                O[n][2] *= aBl; O[n][3] *= aBl;
            }

            const uint32_t stV = stK + 2 * KARR;
#pragma unroll
            for (int ks = 0; ks < 4; ks++) {
                uint32_t ph[4], pl[4];
                {
                    const int j0 = 2 * ks, j1 = 2 * ks + 1;
                    float p00 = accS[j0][0], p01 = accS[j0][1];
                    float p02 = accS[j0][2], p03 = accS[j0][3];
                    float p10 = accS[j1][0], p11 = accS[j1][1];
                    float p12 = accS[j1][2], p13 = accS[j1][3];
                    ph[0] = pack_bf16(p00, p01);
                    ph[1] = pack_bf16(p02, p03);
                    ph[2] = pack_bf16(p10, p11);
                    ph[3] = pack_bf16(p12, p13);
                    __nv_bfloat162* h;
                    h = (__nv_bfloat162*)&ph[0];
                    pl[0] = pack_bf16(p00 - __bfloat162float(h->x), p01 - __bfloat162float(h->y));
                    h = (__nv_bfloat162*)&ph[1];
                    pl[1] = pack_bf16(p02 - __bfloat162float(h->x), p03 - __bfloat162float(h->y));
                    h = (__nv_bfloat162*)&ph[2];
                    pl[2] = pack_bf16(p10 - __bfloat162float(h->x), p11 - __bfloat162float(h->y));
                    h = (__nv_bfloat162*)&ph[3];
                    pl[3] = pack_bf16(p12 - __bfloat162float(h->x), p13 - __bfloat162float(h->y));
                }

                uint32_t vh[16][2], vl[16][2];
                uint32_t t0, t1, t2, t3;
#pragma unroll
                for (int nj = 0; nj < 8; nj++) {
                    uint32_t aV = stV + (((ks * 16 + lrow) * KP) + nj * 16 + lcol8) * 2;
                    LDSM_X4_T(t0, t1, t2, t3, aV);
                    vh[2*nj][0] = t0; vh[2*nj][1] = t1;
                    vh[2*nj+1][0] = t2; vh[2*nj+1][1] = t3;
                    LDSM_X4_T(t0, t1, t2, t3, aV + KARR);
                    vl[2*nj][0] = t0; vl[2*nj][1] = t1;
                    vl[2*nj+1][0] = t2; vl[2*nj+1][1] = t3;
                }
#pragma unroll
                for (int n = 0; n < 16; n++) {
                    MMA16816(O[n], ph, vh[n]);
                    MMA16816(O[n], pl, vh[n]);
                    MMA16816(O[n], ph, vl[n]);
                }
            }
        }
    }

    float* po = g_po + (size_t)j * M_TOT * H_;
    const int rowA = q0 + 16 * w + rA;
    const size_t grA = (size_t)b * T_ + rowA;
#pragma unroll
    for (int n = 0; n < 16; n++) {
        int col = n * 8 + cq;
        *(float2*)&po[grA * H_ + col]       = make_float2(O[n][0], O[n][1]);
        *(float2*)&po[(grA + 8) * H_ + col] = make_float2(O[n][2], O[n][3]);
    }
    if ((lane & 3) == 0) {
        g_pm[(size_t)j * M_TOT + grA]     = mA;
        g_pm[(size_t)j * M_TOT + grA + 8] = mB;
        g_pl[(size_t)j * M_TOT + grA]     = lA;
        g_pl[(size_t)j * M_TOT + grA + 8] = lB;
    }
}

// ---------------------------------------------------------------------------
// attn_merge: combine NSPLIT partials.
// ---------------------------------------------------------------------------
__global__ __launch_bounds__(256) void attn_merge(float* __restrict__ out)
{
    size_t idx = (size_t)blockIdx.x * 256 + threadIdx.x;
    size_t row = idx >> 5;
    int c4 = (int)(idx & 31) * 4;

    float mv[NSPLIT], lv[NSPLIT];
    float m = -1e30f;
#pragma unroll
    for (int j = 0; j < NSPLIT; j++) {
        mv[j] = g_pm[(size_t)j * M_TOT + row];
        lv[j] = g_pl[(size_t)j * M_TOT + row];
        m = fmaxf(m, mv[j]);
    }
    float wsum = 0.f;
    float wv[NSPLIT];
#pragma unroll
    for (int j = 0; j < NSPLIT; j++) {
        wv[j] = __expf(mv[j] - m);
        wsum += wv[j] * lv[j];
    }
    float inv = 1.f / wsum;

    float4 o = make_float4(0.f, 0.f, 0.f, 0.f);
#pragma unroll
    for (int j = 0; j < NSPLIT; j++) {
        float4 a = *(float4*)&g_po[(size_t)j * M_TOT * H_ + row * H_ + c4];
        o.x += wv[j] * a.x;
        o.y += wv[j] * a.y;
        o.z += wv[j] * a.z;
        o.w += wv[j] * a.w;
    }
    o.x *= inv; o.y *= inv; o.z *= inv; o.w *= inv;
    *(float4*)&out[row * H_ + c4] = o;
}

// ---------------------------------------------------------------------------
extern "C" void kernel_launch(void* const* d_in, const int* in_sizes, int n_in,
                              void* d_out, int out_size)
{
    const float* x  = (const float*)d_in[0];
    const float* Wq = (const float*)d_in[1];
    const float* Wk = (const float*)d_in[2];
    const float* Wv = (const float*)d_in[3];
    float* out = (float*)d_out;

    prep_w<<<(3 * H_ * D_ + 255) / 256, 256>>>(Wq, Wk, Wv);

    cudaFuncSetAttribute(proj_mma, cudaFuncAttributeMaxDynamicSharedMemorySize,
                         PSMEM_BYTES);
    proj_mma<<<dim3(M_TOT / 128, 3), 256, PSMEM_BYTES>>>(x);

    cudaFuncSetAttribute(attn_part, cudaFuncAttributeMaxDynamicSharedMemorySize,
                         ATTN_SMEM);
    attn_part<<<32 * B_ * NSPLIT, 256, ATTN_SMEM>>>();

    attn_merge<<<M_TOT * 32 / 256, 256>>>(out);
}